// round 1
// baseline (speedup 1.0000x reference)
#include <cuda_runtime.h>

// out[n, d] = x[n, d] + params[d]
// N = 16384, D = 4096, fp32. Pure HBM-streaming broadcast add.
// Vectorized float4; params column index = (float4_idx & (D/4 - 1)) since D/4 = 1024 is pow2.

#define D_DIM 4096
#define DV (D_DIM / 4)          // 1024 float4 per row
#define THREADS 256

__global__ __launch_bounds__(THREADS) void add_bias_kernel(
    const float4* __restrict__ x,
    const float4* __restrict__ params,
    float4* __restrict__ out,
    int total_v)                 // total float4 elements
{
    int stride = gridDim.x * blockDim.x;
    int i = blockIdx.x * blockDim.x + threadIdx.x;
    #pragma unroll 4
    for (; i < total_v; i += stride) {
        float4 xv = x[i];
        float4 pv = __ldg(&params[i & (DV - 1)]);
        float4 r;
        r.x = xv.x + pv.x;
        r.y = xv.y + pv.y;
        r.z = xv.z + pv.z;
        r.w = xv.w + pv.w;
        out[i] = r;
    }
}

extern "C" void kernel_launch(void* const* d_in, const int* in_sizes, int n_in,
                              void* d_out, int out_size)
{
    const float4* x      = (const float4*)d_in[0];
    const float4* params = (const float4*)d_in[1];
    float4* out          = (float4*)d_out;

    int total_v = out_size / 4;           // 16384*4096/4 = 16,777,216 float4

    // ~8 float4 per thread: enough ILP/MLP to hide DRAM latency, full-chip grid.
    int blocks = (total_v + THREADS * 8 - 1) / (THREADS * 8);
    add_bias_kernel<<<blocks, THREADS>>>(x, params, out, total_v);
}

// round 2
// speedup vs baseline: 1.0248x; 1.0248x over previous
#include <cuda_runtime.h>

// out[n, d] = x[n, d] + params[d],  N=16384, D=4096, fp32.
// HBM-streaming broadcast add. Each block owns 1024 contiguous float4s
// (exactly one params period since D/4 = 1024), each thread handles 4
// independent float4s -> front-batched LDG.E.128 (high MLP), streaming
// cache hints on the zero-reuse x/out streams.

#define D_DIM   4096
#define DV      (D_DIM / 4)     // 1024 float4 per row
#define THREADS 256
#define VPT     4               // float4 per thread
#define VPB     (THREADS * VPT) // 1024 float4 per block == DV

__global__ __launch_bounds__(THREADS) void add_bias_kernel(
    const float4* __restrict__ x,
    const float4* __restrict__ params,
    float4* __restrict__ out,
    int total_v)
{
    int base = blockIdx.x * VPB;
    int tid  = threadIdx.x;

    if (base + VPB <= total_v) {
        // Fast path: no bounds checks, all loads independent & front-batched.
        float4 xv[VPT], pv[VPT];
        #pragma unroll
        for (int k = 0; k < VPT; k++) {
            int i = base + tid + k * THREADS;
            xv[k] = __ldcs(&x[i]);                       // streaming: no reuse
            pv[k] = __ldg(&params[tid + k * THREADS]);   // L1-resident, same for all blocks
        }
        #pragma unroll
        for (int k = 0; k < VPT; k++) {
            int i = base + tid + k * THREADS;
            float4 r;
            r.x = xv[k].x + pv[k].x;
            r.y = xv[k].y + pv[k].y;
            r.z = xv[k].z + pv[k].z;
            r.w = xv[k].w + pv[k].w;
            __stcs(&out[i], r);
        }
    } else {
        // Tail (not taken for the fixed 16384x4096 shape, kept for safety).
        for (int k = 0; k < VPT; k++) {
            int i = base + tid + k * THREADS;
            if (i < total_v) {
                float4 xv = x[i];
                float4 pv = __ldg(&params[i & (DV - 1)]);
                float4 r;
                r.x = xv.x + pv.x;
                r.y = xv.y + pv.y;
                r.z = xv.z + pv.z;
                r.w = xv.w + pv.w;
                out[i] = r;
            }
        }
    }
}

extern "C" void kernel_launch(void* const* d_in, const int* in_sizes, int n_in,
                              void* d_out, int out_size)
{
    const float4* x      = (const float4*)d_in[0];
    const float4* params = (const float4*)d_in[1];
    float4* out          = (float4*)d_out;

    int total_v = out_size / 4;                 // 16,777,216 float4
    int blocks  = (total_v + VPB - 1) / VPB;    // 16384
    add_bias_kernel<<<blocks, THREADS>>>(x, params, out, total_v);
}